// round 14
// baseline (speedup 1.0000x reference)
#include <cuda_runtime.h>
#include <math.h>
#include <cstdint>

#define EPSN 1e-5f

// ---------------- scratch (device globals; no allocation allowed) ----------------
__device__ float g_act1[64*32*64*200];   // conv1+pool output (B,32,64,200)
__device__ float g_w2f[18432];           // conv2 folded weights [(ic*9+k)*64 + oc]
__device__ float g_bias[64];
__device__ float g_part[64*16*64*112];   // conv2 per-ht 2-row partial sums (B,ht16,oc,pcol)
__device__ float g_out2t[64*100*64];     // freq-mean, transposed (b,t,oc) for coalesced proj
__device__ float g_h3[64*100*256];       // proj+LN output (B,100,256)
__device__ float g_cur1[64*50*256];      // fc1 output (B,50,256)
__device__ float g_cur2[64*50*128];      // fc2 output (float, = acc2+fb)
__device__ float g_s2[64*50*128];        // layer-2 spikes
__device__ double g_c3[64*50*2];         // fco currents (double)

// accurate rsqrt matching lax.rsqrt(v + EPS) semantics
__device__ __forceinline__ float rsqrt_acc(float v) {
    float vf = v + EPSN;
    return (float)(1.0 / sqrt((double)vf));
}

// ---------------- bsetup (byte-identical to R13) ----------------
__global__ __launch_bounds__(256) void bsetup_kernel(
    const float* __restrict__ c2w, const float* __restrict__ c2b,
    const float* __restrict__ g, const float* __restrict__ bb,
    const float* __restrict__ m, const float* __restrict__ v)
{
    int idx = blockIdx.x * 256 + threadIdx.x;
    if (idx < 18432) {
        int oc = idx & 63; int rest = idx >> 6;
        int k = rest % 9;  int ic = rest / 9;
        float s = g[oc] * rsqrt_acc(v[oc]);
        g_w2f[idx] = c2w[(oc*32 + ic)*9 + k] * s;
    }
    if (blockIdx.x == 0 && threadIdx.x < 64) {
        int oc = threadIdx.x;
        float s = g[oc] * rsqrt_acc(v[oc]);
        g_bias[oc] = (c2b[oc] - m[oc]) * s + bb[oc];
    }
}

// ---------------- conv1 (byte-identical to R13) ----------------
__global__ __launch_bounds__(256) void conv1_kernel(
    const float* __restrict__ x, const float* __restrict__ c1w, const float* __restrict__ c1b,
    const float* __restrict__ g, const float* __restrict__ bb,
    const float* __restrict__ m, const float* __restrict__ v)
{
    __shared__ float in_s[10][132];
    __shared__ float w_s[32*9];
    __shared__ float b_s[32];
    int tid = threadIdx.x;
    int b   = blockIdx.z;
    int PH0 = blockIdx.y * 4;
    int PW0 = blockIdx.x * 64;

    if (tid < 32) {
        float r = rsqrt_acc(v[tid]);
        float s = g[tid] * r;
        b_s[tid] = (c1b[tid] - m[tid]) * s + bb[tid];
        #pragma unroll
        for (int k = 0; k < 9; k++) w_s[tid*9+k] = c1w[tid*9+k] * s;
    }
    const float* xb = x + b * 128 * 400;
    for (int idx = tid; idx < 10*130; idx += 256) {
        int r = idx / 130, c = idx - r*130;
        int gh = PH0*2 - 1 + r, gw = PW0*2 - 1 + c;
        float val = 0.f;
        if (gh >= 0 && gh < 128 && gw >= 0 && gw < 400) val = xb[gh*400 + gw];
        in_s[r][c] = val;
    }
    __syncthreads();

    int pwl = tid & 63, phl = tid >> 6;
    int gpw = PW0 + pwl;
    bool valid = gpw < 200;

    float rin[4][4];
    #pragma unroll
    for (int r = 0; r < 4; r++)
        #pragma unroll
        for (int c = 0; c < 4; c++)
            rin[r][c] = in_s[phl*2 + r][pwl*2 + c];

    float* outp = &g_act1[((b*32)*64 + PH0 + phl)*200 + gpw];
    #pragma unroll 4
    for (int oc = 0; oc < 32; oc++) {
        float c00=0.f, c01=0.f, c10=0.f, c11=0.f;
        #pragma unroll
        for (int kh = 0; kh < 3; kh++)
            #pragma unroll
            for (int kw = 0; kw < 3; kw++) {
                float w = w_s[oc*9 + kh*3 + kw];
                c00 = fmaf(rin[kh  ][kw  ], w, c00);
                c01 = fmaf(rin[kh  ][kw+1], w, c01);
                c10 = fmaf(rin[kh+1][kw  ], w, c10);
                c11 = fmaf(rin[kh+1][kw+1], w, c11);
            }
        float mx  = fmaxf(fmaxf(c00, c01), fmaxf(c10, c11));
        float val = fmaxf(mx + b_s[oc], 0.f);
        if (valid) outp[oc*64*200] = val;
    }
}

// ---------------- conv2: persistent CTAs (byte-identical to R13) ----------------
#define CV2_SMEM (27456*4)
#define CV2_GRID 296
__global__ __launch_bounds__(256, 2) void conv2_kernel()
{
    extern __shared__ float sm[];
    float* w_s  = sm;
    float* in_s = sm + 18432;
    float* red  = sm + 25344;
    float* b2p  = sm + 27392;

    int tid = threadIdx.x;
    if (tid < 64) b2p[tid] = g_bias[tid];
    {
        const float4* src = (const float4*)g_w2f;
        float4* dst = (float4*)w_s;
        #pragma unroll
        for (int j = 0; j < 18; j++) dst[tid + j*256] = src[tid + j*256];
    }
    for (int idx = tid; idx < 192; idx += 256) {
        in_s[idx*36 + 34] = 0.f; in_s[idx*36 + 35] = 0.f;
    }

    int ocb = (tid >> 4) * 4;
    int sp = tid & 15;
    int hg = sp >> 3, wg = sp & 7;

    for (int tile = blockIdx.x; tile < 7168; tile += CV2_GRID) {
        int wt = tile % 7;
        int rest = tile / 7;
        int ht = rest & 15;
        int b = rest >> 4;
        int H0 = ht * 4, W0 = wt * 32;

        for (int idx = tid; idx < 6528; idx += 256) {
            int c = idx % 34; int r = (idx / 34) % 6; int ic = idx / 204;
            int gh = H0 - 1 + r, gw = W0 - 1 + c;
            float val = 0.f;
            if (gh >= 0 && gh < 64 && gw >= 0 && gw < 200)
                val = g_act1[((b*32 + ic)*64 + gh)*200 + gw];
            in_s[(ic*6 + r)*36 + c] = val;
        }
        __syncthreads();

        float acc[4][8];
        #pragma unroll
        for (int o = 0; o < 4; o++)
            #pragma unroll
            for (int s = 0; s < 8; s++) acc[o][s] = 0.f;

        for (int ic = 0; ic < 32; ic++) {
            float rin[4][8];
            const float* ip = in_s + ic*216 + (hg*2)*36 + wg*4;
            #pragma unroll
            for (int r = 0; r < 4; r++) {
                float4 a  = *(const float4*)(ip + r*36);
                float4 bq = *(const float4*)(ip + r*36 + 4);
                rin[r][0]=a.x;  rin[r][1]=a.y;  rin[r][2]=a.z;  rin[r][3]=a.w;
                rin[r][4]=bq.x; rin[r][5]=bq.y; rin[r][6]=bq.z; rin[r][7]=bq.w;
            }
            const float* wp = w_s + ic*576 + ocb;
            float tmp[4][8];
            {
                float4 wa = *(const float4*)(wp);
                #pragma unroll
                for (int dh = 0; dh < 2; dh++)
                    #pragma unroll
                    for (int dw = 0; dw < 4; dw++) {
                        float xv = rin[dh][dw];
                        int s = dh*4 + dw;
                        tmp[0][s] = wa.x * xv; tmp[1][s] = wa.y * xv;
                        tmp[2][s] = wa.z * xv; tmp[3][s] = wa.w * xv;
                    }
            }
            #pragma unroll
            for (int k = 1; k < 9; k++) {
                const int kh = k / 3, kw = k % 3;
                float4 wa = *(const float4*)(wp + k*64);
                #pragma unroll
                for (int dh = 0; dh < 2; dh++)
                    #pragma unroll
                    for (int dw = 0; dw < 4; dw++) {
                        float xv = rin[kh+dh][kw+dw];
                        int s = dh*4 + dw;
                        tmp[0][s] = fmaf(wa.x, xv, tmp[0][s]);
                        tmp[1][s] = fmaf(wa.y, xv, tmp[1][s]);
                        tmp[2][s] = fmaf(wa.z, xv, tmp[2][s]);
                        tmp[3][s] = fmaf(wa.w, xv, tmp[3][s]);
                    }
            }
            #pragma unroll
            for (int o = 0; o < 4; o++)
                #pragma unroll
                for (int s = 0; s < 8; s++) acc[o][s] += tmp[o][s];
        }

        #pragma unroll
        for (int o = 0; o < 4; o++) {
            int oc = ocb + o;
            float bias = b2p[oc];
            #pragma unroll
            for (int pw2 = 0; pw2 < 2; pw2++) {
                float mx = fmaxf(fmaxf(acc[o][0 + 2*pw2], acc[o][0 + 2*pw2 + 1]),
                                 fmaxf(acc[o][4 + 2*pw2], acc[o][4 + 2*pw2 + 1]));
                float val = fmaxf(mx + bias, 0.f);
                red[((oc)*16 + wg*2 + pw2)*2 + hg] = val;
            }
        }
        __syncthreads();
        for (int idx = tid; idx < 1024; idx += 256) {
            int oc = idx >> 4, pcol = idx & 15;
            const float* rp = &red[idx*2];
            float partial = rp[0] + rp[1];
            g_part[((b*16 + ht)*64 + oc)*112 + wt*16 + pcol] = partial;
        }
    }
}

// ---------------- freq mean: same tree, writes TRANSPOSED layout (b,t,oc) ----------------
__global__ __launch_bounds__(256) void freqmean_kernel() {
    int i = blockIdx.x * blockDim.x + threadIdx.x;
    if (i >= 64*64*100) return;
    int col = i % 100; int oc = (i / 100) & 63; int b = i / 6400;
    const float* pp = &g_part[((b*16)*64 + oc)*112 + col];
    const int st = 64*112;
    float p0 = pp[0*st]  + pp[1*st];
    float p1 = pp[2*st]  + pp[3*st];
    float p2 = pp[4*st]  + pp[5*st];
    float p3 = pp[6*st]  + pp[7*st];
    float p4 = pp[8*st]  + pp[9*st];
    float p5 = pp[10*st] + pp[11*st];
    float p6 = pp[12*st] + pp[13*st];
    float p7 = pp[14*st] + pp[15*st];
    float s = ((p0 + p1) + (p2 + p3)) + ((p4 + p5) + (p6 + p7));
    g_out2t[(b*100 + col)*64 + oc] = s * (1.f/32.f);   // same value, transposed address
}

// ---------------- channel_proj + LN (coalesced xr fill; per-row arithmetic identical) ----------------
__global__ __launch_bounds__(256) void proj_kernel(
    const float* __restrict__ pw, const float* __restrict__ pb,
    const float* __restrict__ plg, const float* __restrict__ plb)
{
    __shared__ float xr[8][64];
    __shared__ float redA[8][8];
    __shared__ float redB[8][8];
    int tid = threadIdx.x;
    int lane = tid & 31, w = tid >> 5;
    int row0 = blockIdx.x * 8;
    for (int idx = tid; idx < 8*64; idx += 256) {
        int r = idx >> 6, ic = idx & 63;
        xr[r][ic] = g_out2t[(row0 + r)*64 + ic];   // coalesced
    }
    __syncthreads();

    float acc[8];
    #pragma unroll
    for (int r = 0; r < 8; r++) acc[r] = 0.f;
    for (int kc = 0; kc < 8; kc++) {
        float tmp[8];
        int k0 = kc * 8;
        float w0 = pw[k0*256 + tid];
        #pragma unroll
        for (int r = 0; r < 8; r++) tmp[r] = xr[r][k0] * w0;
        #pragma unroll
        for (int j = 1; j < 8; j++) {
            float wv = pw[(k0+j)*256 + tid];
            #pragma unroll
            for (int r = 0; r < 8; r++) tmp[r] = fmaf(xr[r][k0+j], wv, tmp[r]);
        }
        #pragma unroll
        for (int r = 0; r < 8; r++) acc[r] += tmp[r];
    }
    float bias = pb[tid];
    #pragma unroll
    for (int r = 0; r < 8; r++) acc[r] += bias;

    #pragma unroll
    for (int r = 0; r < 8; r++) {
        float val = acc[r];
        #pragma unroll
        for (int o = 16; o; o >>= 1) val += __shfl_down_sync(0xffffffffu, val, o);
        if (lane == 0) redA[r][w] = val;
    }
    __syncthreads();
    float mean[8];
    #pragma unroll
    for (int r = 0; r < 8; r++) {
        float a = ((redA[r][0] + redA[r][1]) + (redA[r][2] + redA[r][3]))
                + ((redA[r][4] + redA[r][5]) + (redA[r][6] + redA[r][7]));
        mean[r] = a * (1.f/256.f);
    }
    float d[8];
    #pragma unroll
    for (int r = 0; r < 8; r++) {
        d[r] = acc[r] - mean[r];
        float val = d[r]*d[r];
        #pragma unroll
        for (int o = 16; o; o >>= 1) val += __shfl_down_sync(0xffffffffu, val, o);
        if (lane == 0) redB[r][w] = val;
    }
    __syncthreads();
    float gv = plg[tid], bv = plb[tid];
    #pragma unroll
    for (int r = 0; r < 8; r++) {
        float a = ((redB[r][0] + redB[r][1]) + (redB[r][2] + redB[r][3]))
                + ((redB[r][4] + redB[r][5]) + (redB[r][6] + redB[r][7]));
        float var = a * (1.f/256.f);
        g_h3[(row0 + r)*256 + tid] = d[r] * rsqrt_acc(var) * gv + bv;
    }
}

// ---------------- interp + LN + fc1 (byte-identical to R13) ----------------
__global__ __launch_bounds__(256) void fc1_kernel(
    const float* __restrict__ ing, const float* __restrict__ inb,
    const float* __restrict__ fc1w, const float* __restrict__ fc1b)
{
    __shared__ float cr[8*256];
    __shared__ float redA[8][8];
    __shared__ float redB[8][8];
    int tid = threadIdx.x;
    int lane = tid & 31, w = tid >> 5;
    int row0 = blockIdx.x * 8;
    float gv = ing[tid], bv = inb[tid];

    float a[8];
    #pragma unroll
    for (int r = 0; r < 8; r++) {
        int row = row0 + r; int b = row / 50, t = row - b*50;
        a[r] = 0.5f * (g_h3[(b*100 + 2*t)*256 + tid] + g_h3[(b*100 + 2*t + 1)*256 + tid]);
    }
    #pragma unroll
    for (int r = 0; r < 8; r++) {
        float val = a[r];
        #pragma unroll
        for (int o = 16; o; o >>= 1) val += __shfl_down_sync(0xffffffffu, val, o);
        if (lane == 0) redA[r][w] = val;
    }
    __syncthreads();
    float mean[8];
    #pragma unroll
    for (int r = 0; r < 8; r++) {
        float s = ((redA[r][0] + redA[r][1]) + (redA[r][2] + redA[r][3]))
                + ((redA[r][4] + redA[r][5]) + (redA[r][6] + redA[r][7]));
        mean[r] = s * (1.f/256.f);
    }
    float d[8];
    #pragma unroll
    for (int r = 0; r < 8; r++) {
        d[r] = a[r] - mean[r];
        float val = d[r]*d[r];
        #pragma unroll
        for (int o = 16; o; o >>= 1) val += __shfl_down_sync(0xffffffffu, val, o);
        if (lane == 0) redB[r][w] = val;
    }
    __syncthreads();
    #pragma unroll
    for (int r = 0; r < 8; r++) {
        float s = ((redB[r][0] + redB[r][1]) + (redB[r][2] + redB[r][3]))
                + ((redB[r][4] + redB[r][5]) + (redB[r][6] + redB[r][7]));
        float var = s * (1.f/256.f);
        cr[r*256 + tid] = d[r] * rsqrt_acc(var) * gv + bv;
    }
    __syncthreads();

    float acc[8];
    #pragma unroll
    for (int r = 0; r < 8; r++) acc[r] = 0.f;
    for (int kc = 0; kc < 16; kc++) {
        float tmp[8];
        int k0 = kc * 16;
        float w0 = fc1w[k0*256 + tid];
        #pragma unroll
        for (int r = 0; r < 8; r++) tmp[r] = cr[r*256 + k0] * w0;
        #pragma unroll
        for (int j = 1; j < 16; j++) {
            float wv = fc1w[(k0+j)*256 + tid];
            #pragma unroll
            for (int r = 0; r < 8; r++) tmp[r] = fmaf(cr[r*256 + k0 + j], wv, tmp[r]);
        }
        #pragma unroll
        for (int r = 0; r < 8; r++) acc[r] += tmp[r];
    }
    float bias = fc1b[tid];
    #pragma unroll
    for (int r = 0; r < 8; r++) g_cur1[(row0 + r)*256 + tid] = acc[r] + bias;
}

// ---------------- scan A-E (byte-identical to R13) ----------------
__global__ __launch_bounds__(256) void scanA_kernel(
    const float* __restrict__ pb1, const float* __restrict__ pt1, float* __restrict__ out)
{
    int b = blockIdx.x, u = threadIdx.x;
    double b1 = (double)fminf(fmaxf(*pb1, 0.f), 1.f), t1 = (double)*pt1;
    double m1 = 0.0;
    const float* curp = &g_cur1[(b*50)*256 + u];
    float* spkp = &out[128 + (b*50)*256 + u];
    for (int t = 0; t < 50; t++) {
        double c = (double)curp[t*256];
        double r1 = (m1 > t1) ? t1 : 0.0;
        m1 = b1*m1 + c - r1;
        spkp[t*256] = (m1 - t1 > 0.0) ? 1.f : 0.f;
    }
}

__global__ __launch_bounds__(256) void scanB_kernel(
    const float* __restrict__ out_spk, const float* __restrict__ fc2w,
    const float* __restrict__ fc2b)
{
    __shared__ float s1s[2][256];
    int tid = threadIdx.x;
    int r0 = blockIdx.x * 2;
    int lr = tid >> 7, j = tid & 127;
    for (int i = tid; i < 512; i += 256)
        s1s[i >> 8][i & 255] = out_spk[128 + (r0 + (i >> 8))*256 + (i & 255)];
    __syncthreads();

    const float* w2col = fc2w + j;
    const float* sp = s1s[lr];
    float acc2 = 0.f;
    #pragma unroll
    for (int kc = 0; kc < 16; kc++) {
        int k0 = kc * 16;
        float tt = sp[k0] * w2col[k0*128];
        #pragma unroll
        for (int jj = 1; jj < 16; jj++)
            tt = fmaf(sp[k0 + jj], w2col[(k0 + jj)*128], tt);
        acc2 += tt;
    }
    g_cur2[(r0 + lr)*128 + j] = acc2 + fc2b[j];
}

__global__ __launch_bounds__(256) void scanC_kernel(
    const float* __restrict__ pb2, const float* __restrict__ pt2)
{
    int idx = blockIdx.x * 256 + threadIdx.x;
    int b = idx >> 7, j = idx & 127;
    double b2 = (double)fminf(fmaxf(*pb2, 0.f), 1.f), t2 = (double)*pt2;
    double m2 = 0.0;
    for (int t = 0; t < 50; t++) {
        double cur2 = (double)g_cur2[(b*50 + t)*128 + j];
        double r2 = (m2 > t2) ? t2 : 0.0;
        m2 = b2*m2 + cur2 - r2;
        g_s2[(b*50 + t)*128 + j] = (m2 - t2 > 0.0) ? 1.f : 0.f;
    }
}

__global__ __launch_bounds__(128) void scanD_kernel(
    const float* __restrict__ fcow, const float* __restrict__ fcob)
{
    __shared__ double red2[4][2];
    int row = blockIdx.x;
    int tid = threadIdx.x, lane = tid & 31, w = tid >> 5;
    float s2 = g_s2[row*128 + tid];
    float fw0 = fcow[tid*2], fw1 = fcow[tid*2 + 1];
    double s2d = (double)s2;
    double v0 = s2d * (double)fw0, v1 = s2d * (double)fw1;
    #pragma unroll
    for (int o = 16; o; o >>= 1) {
        v0 += __shfl_down_sync(0xffffffffu, v0, o);
        v1 += __shfl_down_sync(0xffffffffu, v1, o);
    }
    if (lane == 0) { red2[w][0] = v0; red2[w][1] = v1; }
    __syncthreads();
    if (tid == 0) {
        g_c3[row*2]     = (double)fcob[0] + ((red2[0][0] + red2[1][0]) + (red2[2][0] + red2[3][0]));
        g_c3[row*2 + 1] = (double)fcob[1] + ((red2[0][1] + red2[1][1]) + (red2[2][1] + red2[3][1]));
    }
}

__global__ __launch_bounds__(128) void scanE_kernel(
    const float* __restrict__ pb3, const float* __restrict__ pt3, float* __restrict__ out)
{
    int tid = threadIdx.x;
    int b = tid >> 1, cls = tid & 1;
    double b3 = (double)fminf(fmaxf(*pb3, 0.f), 1.f), t3 = (double)*pt3;
    double mo = 0.0, l = 0.0;
    for (int t = 0; t < 50; t++) {
        double c3 = g_c3[(b*50 + t)*2 + cls];
        double r = (mo > t3) ? t3 : 0.0;
        mo = b3*mo + c3 - r;
        l += mo;
    }
    out[b*2 + cls] = (float)l;
}

// ---------------- launch ----------------
extern "C" void kernel_launch(void* const* d_in, const int* in_sizes, int n_in,
                              void* d_out, int out_size)
{
    const float* x    = (const float*)d_in[0];
    const float* c1w  = (const float*)d_in[1];
    const float* c1b  = (const float*)d_in[2];
    const float* bn1g = (const float*)d_in[3];
    const float* bn1b = (const float*)d_in[4];
    const float* bn1m = (const float*)d_in[5];
    const float* bn1v = (const float*)d_in[6];
    const float* c2w  = (const float*)d_in[7];
    const float* c2b  = (const float*)d_in[8];
    const float* bn2g = (const float*)d_in[9];
    const float* bn2b = (const float*)d_in[10];
    const float* bn2m = (const float*)d_in[11];
    const float* bn2v = (const float*)d_in[12];
    const float* pw   = (const float*)d_in[13];
    const float* pb   = (const float*)d_in[14];
    const float* plg  = (const float*)d_in[15];
    const float* plb  = (const float*)d_in[16];
    const float* ing  = (const float*)d_in[17];
    const float* inb  = (const float*)d_in[18];
    const float* fc1w = (const float*)d_in[19];
    const float* fc1b = (const float*)d_in[20];
    const float* fc2w = (const float*)d_in[21];
    const float* fc2b = (const float*)d_in[22];
    const float* fcow = (const float*)d_in[23];
    const float* fcob = (const float*)d_in[24];
    const float* beta1 = (const float*)d_in[25];
    const float* thr1  = (const float*)d_in[26];
    const float* beta2 = (const float*)d_in[27];
    const float* thr2  = (const float*)d_in[28];
    const float* beta3 = (const float*)d_in[29];
    const float* thr3  = (const float*)d_in[30];
    float* out = (float*)d_out;

    cudaFuncSetAttribute(conv2_kernel, cudaFuncAttributeMaxDynamicSharedMemorySize, CV2_SMEM);

    bsetup_kernel<<<72, 256>>>(c2w, c2b, bn2g, bn2b, bn2m, bn2v);
    conv1_kernel<<<dim3(4, 16, 64), 256>>>(x, c1w, c1b, bn1g, bn1b, bn1m, bn1v);
    conv2_kernel<<<CV2_GRID, 256, CV2_SMEM>>>();
    freqmean_kernel<<<1600, 256>>>();
    proj_kernel<<<800, 256>>>(pw, pb, plg, plb);
    fc1_kernel<<<400, 256>>>(ing, inb, fc1w, fc1b);
    scanA_kernel<<<64, 256>>>(beta1, thr1, out);
    scanB_kernel<<<1600, 256>>>(out, fc2w, fc2b);
    scanC_kernel<<<32, 256>>>(beta2, thr2);
    scanD_kernel<<<3200, 128>>>(fcow, fcob);
    scanE_kernel<<<1, 128>>>(beta3, thr3, out);
}

// round 16
// speedup vs baseline: 1.0768x; 1.0768x over previous
#include <cuda_runtime.h>
#include <math.h>
#include <cstdint>

#define EPSN 1e-5f

// ---------------- scratch (device globals; no allocation allowed) ----------------
__device__ float g_act1[64*32*64*200];   // conv1+pool output (B,32,64,200)
__device__ float g_w2f[18432];           // conv2 folded weights [(ic*9+k)*64 + oc]
__device__ float g_bias[64];
__device__ float g_part[64*16*64*112];   // conv2 per-2-pooled-row partials (B,16,oc,pcol)
__device__ float g_out2[64*64*100];      // conv2+pool+freq-mean output (B,64,100)
__device__ float g_h3[64*100*256];       // proj+LN output (B,100,256)
__device__ float g_cur1[64*50*256];      // fc1 output (B,50,256)
__device__ float g_cur2[64*50*128];      // fc2 output (float, = acc2+fb)
__device__ float g_s2[64*50*128];        // layer-2 spikes
__device__ double g_c3[64*50*2];         // fco currents (double)

// accurate rsqrt matching lax.rsqrt(v + EPS) semantics
__device__ __forceinline__ float rsqrt_acc(float v) {
    float vf = v + EPSN;
    return (float)(1.0 / sqrt((double)vf));
}

// ---------------- bsetup (byte-identical to R13) ----------------
__global__ __launch_bounds__(256) void bsetup_kernel(
    const float* __restrict__ c2w, const float* __restrict__ c2b,
    const float* __restrict__ g, const float* __restrict__ bb,
    const float* __restrict__ m, const float* __restrict__ v)
{
    int idx = blockIdx.x * 256 + threadIdx.x;
    if (idx < 18432) {
        int oc = idx & 63; int rest = idx >> 6;
        int k = rest % 9;  int ic = rest / 9;
        float s = g[oc] * rsqrt_acc(v[oc]);
        g_w2f[idx] = c2w[(oc*32 + ic)*9 + k] * s;
    }
    if (blockIdx.x == 0 && threadIdx.x < 64) {
        int oc = threadIdx.x;
        float s = g[oc] * rsqrt_acc(v[oc]);
        g_bias[oc] = (c2b[oc] - m[oc]) * s + bb[oc];
    }
}

// ---------------- conv1 (byte-identical to R13) ----------------
__global__ __launch_bounds__(256) void conv1_kernel(
    const float* __restrict__ x, const float* __restrict__ c1w, const float* __restrict__ c1b,
    const float* __restrict__ g, const float* __restrict__ bb,
    const float* __restrict__ m, const float* __restrict__ v)
{
    __shared__ float in_s[10][132];
    __shared__ float w_s[32*9];
    __shared__ float b_s[32];
    int tid = threadIdx.x;
    int b   = blockIdx.z;
    int PH0 = blockIdx.y * 4;
    int PW0 = blockIdx.x * 64;

    if (tid < 32) {
        float r = rsqrt_acc(v[tid]);
        float s = g[tid] * r;
        b_s[tid] = (c1b[tid] - m[tid]) * s + bb[tid];
        #pragma unroll
        for (int k = 0; k < 9; k++) w_s[tid*9+k] = c1w[tid*9+k] * s;
    }
    const float* xb = x + b * 128 * 400;
    for (int idx = tid; idx < 10*130; idx += 256) {
        int r = idx / 130, c = idx - r*130;
        int gh = PH0*2 - 1 + r, gw = PW0*2 - 1 + c;
        float val = 0.f;
        if (gh >= 0 && gh < 128 && gw >= 0 && gw < 400) val = xb[gh*400 + gw];
        in_s[r][c] = val;
    }
    __syncthreads();

    int pwl = tid & 63, phl = tid >> 6;
    int gpw = PW0 + pwl;
    bool valid = gpw < 200;

    float rin[4][4];
    #pragma unroll
    for (int r = 0; r < 4; r++)
        #pragma unroll
        for (int c = 0; c < 4; c++)
            rin[r][c] = in_s[phl*2 + r][pwl*2 + c];

    float* outp = &g_act1[((b*32)*64 + PH0 + phl)*200 + gpw];
    #pragma unroll 4
    for (int oc = 0; oc < 32; oc++) {
        float c00=0.f, c01=0.f, c10=0.f, c11=0.f;
        #pragma unroll
        for (int kh = 0; kh < 3; kh++)
            #pragma unroll
            for (int kw = 0; kw < 3; kw++) {
                float w = w_s[oc*9 + kh*3 + kw];
                c00 = fmaf(rin[kh  ][kw  ], w, c00);
                c01 = fmaf(rin[kh  ][kw+1], w, c01);
                c10 = fmaf(rin[kh+1][kw  ], w, c10);
                c11 = fmaf(rin[kh+1][kw+1], w, c11);
            }
        float mx  = fmaxf(fmaxf(c00, c01), fmaxf(c10, c11));
        float val = fmaxf(mx + b_s[oc], 0.f);
        if (valid) outp[oc*64*200] = val;
    }
}

// ---------------- conv2: persistent CTAs, 8x16 tiles, R13 per-output chain ----------------
// Tile: 64 oc x 8 conv-rows x 16 conv-cols. Thread: 4 oc x 2h x 4w (sp: hg=sp>>2, wg=sp&3).
// smem floats: w_s 18432 | in_s 32*10*20=6400 | red 64*8*4=2048 | b2p 64 = 26944 (107776 B)
#define CV2_SMEM (26944*4)
#define CV2_GRID 296
__global__ __launch_bounds__(256, 2) void conv2_kernel()
{
    extern __shared__ float sm[];
    float* w_s  = sm;                 // [(ic*9+k)*64 + oc]
    float* in_s = sm + 18432;         // [ic][10 rows][20: 18 cols + 2 pad]
    float* red  = sm + 24832;         // [oc][8 pcol][4 hg]
    float* b2p  = sm + 26880;

    int tid = threadIdx.x;
    if (tid < 64) b2p[tid] = g_bias[tid];
    {
        const float4* src = (const float4*)g_w2f;
        float4* dst = (float4*)w_s;
        #pragma unroll
        for (int j = 0; j < 18; j++) dst[tid + j*256] = src[tid + j*256];
    }
    for (int idx = tid; idx < 320; idx += 256) {   // pad cols 18,19 once
        in_s[idx*20 + 18] = 0.f; in_s[idx*20 + 19] = 0.f;
    }

    int ocb = (tid >> 4) * 4;
    int sp = tid & 15;
    int hg = sp >> 2, wg = sp & 3;   // 4 row-pairs x 4 col-quads

    for (int tile = blockIdx.x; tile < 6656; tile += CV2_GRID) {
        int wt = tile % 13;
        int rest = tile / 13;
        int ht = rest & 7;
        int b = rest >> 3;
        int H0 = ht * 8, W0 = wt * 16;

        for (int idx = tid; idx < 5760; idx += 256) {   // 32ic x 10r x 18c
            int c = idx % 18; int r = (idx / 18) % 10; int ic = idx / 180;
            int gh = H0 - 1 + r, gw = W0 - 1 + c;
            float val = 0.f;
            if (gh >= 0 && gh < 64 && gw >= 0 && gw < 200)
                val = g_act1[((b*32 + ic)*64 + gh)*200 + gw];
            in_s[(ic*10 + r)*20 + c] = val;
        }
        __syncthreads();

        float acc[4][8];
        #pragma unroll
        for (int o = 0; o < 4; o++)
            #pragma unroll
            for (int s = 0; s < 8; s++) acc[o][s] = 0.f;

        for (int ic = 0; ic < 32; ic++) {
            float rin[4][8];
            const float* ip = in_s + ic*200 + (hg*2)*20 + wg*4;
            #pragma unroll
            for (int r = 0; r < 4; r++) {
                float4 a  = *(const float4*)(ip + r*20);
                float4 bq = *(const float4*)(ip + r*20 + 4);
                rin[r][0]=a.x;  rin[r][1]=a.y;  rin[r][2]=a.z;  rin[r][3]=a.w;
                rin[r][4]=bq.x; rin[r][5]=bq.y; rin[r][6]=bq.z; rin[r][7]=bq.w;
            }
            const float* wp = w_s + ic*576 + ocb;
            float tmp[4][8];
            // k = 0: init via multiply (R3/R13 chain)
            {
                float4 wa = *(const float4*)(wp);
                #pragma unroll
                for (int dh = 0; dh < 2; dh++)
                    #pragma unroll
                    for (int dw = 0; dw < 4; dw++) {
                        float xv = rin[dh][dw];
                        int s = dh*4 + dw;
                        tmp[0][s] = wa.x * xv; tmp[1][s] = wa.y * xv;
                        tmp[2][s] = wa.z * xv; tmp[3][s] = wa.w * xv;
                    }
            }
            #pragma unroll
            for (int k = 1; k < 9; k++) {
                const int kh = k / 3, kw = k % 3;
                float4 wa = *(const float4*)(wp + k*64);
                #pragma unroll
                for (int dh = 0; dh < 2; dh++)
                    #pragma unroll
                    for (int dw = 0; dw < 4; dw++) {
                        float xv = rin[kh+dh][kw+dw];
                        int s = dh*4 + dw;
                        tmp[0][s] = fmaf(wa.x, xv, tmp[0][s]);
                        tmp[1][s] = fmaf(wa.y, xv, tmp[1][s]);
                        tmp[2][s] = fmaf(wa.z, xv, tmp[2][s]);
                        tmp[3][s] = fmaf(wa.w, xv, tmp[3][s]);
                    }
            }
            #pragma unroll
            for (int o = 0; o < 4; o++)
                #pragma unroll
                for (int s = 0; s < 8; s++) acc[o][s] += tmp[o][s];
        }

        // epilogue: bias + maxpool2x2 + relu -> red[oc][pcol(8)][hg(4)]
        #pragma unroll
        for (int o = 0; o < 4; o++) {
            int oc = ocb + o;
            float bias = b2p[oc];
            #pragma unroll
            for (int pw2 = 0; pw2 < 2; pw2++) {
                float mx = fmaxf(fmaxf(acc[o][0 + 2*pw2], acc[o][0 + 2*pw2 + 1]),
                                 fmaxf(acc[o][4 + 2*pw2], acc[o][4 + 2*pw2 + 1]));
                float val = fmaxf(mx + bias, 0.f);
                red[((oc)*8 + wg*2 + pw2)*4 + hg] = val;
            }
        }
        __syncthreads();
        // two 2-pooled-row partials per (oc,pcol): (hg0+hg1) and (hg2+hg3)
        // -> same sixteen per-(b,oc) slots as R13 (slot 2*ht+pair)
        for (int idx = tid; idx < 1024; idx += 256) {
            int pair = idx & 1, pcol = (idx >> 1) & 7, oc = idx >> 4;
            int gcol = wt*8 + pcol;
            if (gcol < 100) {
                const float* rp = &red[(oc*8 + pcol)*4 + 2*pair];
                float partial = rp[0] + rp[1];
                g_part[((b*16 + ht*2 + pair)*64 + oc)*112 + gcol] = partial;
            }
        }
    }
}

// ---------------- freq mean (byte-identical to R13) ----------------
__global__ __launch_bounds__(256) void freqmean_kernel() {
    int i = blockIdx.x * blockDim.x + threadIdx.x;
    if (i >= 64*64*100) return;
    int col = i % 100; int oc = (i / 100) & 63; int b = i / 6400;
    const float* pp = &g_part[((b*16)*64 + oc)*112 + col];
    const int st = 64*112;
    float p0 = pp[0*st]  + pp[1*st];
    float p1 = pp[2*st]  + pp[3*st];
    float p2 = pp[4*st]  + pp[5*st];
    float p3 = pp[6*st]  + pp[7*st];
    float p4 = pp[8*st]  + pp[9*st];
    float p5 = pp[10*st] + pp[11*st];
    float p6 = pp[12*st] + pp[13*st];
    float p7 = pp[14*st] + pp[15*st];
    float s = ((p0 + p1) + (p2 + p3)) + ((p4 + p5) + (p6 + p7));
    g_out2[i] = s * (1.f/32.f);
}

// ---------------- channel_proj + LN (byte-identical to R13) ----------------
__global__ __launch_bounds__(256) void proj_kernel(
    const float* __restrict__ pw, const float* __restrict__ pb,
    const float* __restrict__ plg, const float* __restrict__ plb)
{
    __shared__ float xr[8][64];
    __shared__ float redA[8][8];
    __shared__ float redB[8][8];
    int tid = threadIdx.x;
    int lane = tid & 31, w = tid >> 5;
    int row0 = blockIdx.x * 8;
    for (int idx = tid; idx < 8*64; idx += 256) {
        int r = idx >> 6, ic = idx & 63;
        int row = row0 + r; int b = row / 100, t = row - b*100;
        xr[r][ic] = g_out2[(b*64 + ic)*100 + t];
    }
    __syncthreads();

    float acc[8];
    #pragma unroll
    for (int r = 0; r < 8; r++) acc[r] = 0.f;
    for (int kc = 0; kc < 8; kc++) {
        float tmp[8];
        int k0 = kc * 8;
        float w0 = pw[k0*256 + tid];
        #pragma unroll
        for (int r = 0; r < 8; r++) tmp[r] = xr[r][k0] * w0;
        #pragma unroll
        for (int j = 1; j < 8; j++) {
            float wv = pw[(k0+j)*256 + tid];
            #pragma unroll
            for (int r = 0; r < 8; r++) tmp[r] = fmaf(xr[r][k0+j], wv, tmp[r]);
        }
        #pragma unroll
        for (int r = 0; r < 8; r++) acc[r] += tmp[r];
    }
    float bias = pb[tid];
    #pragma unroll
    for (int r = 0; r < 8; r++) acc[r] += bias;

    #pragma unroll
    for (int r = 0; r < 8; r++) {
        float val = acc[r];
        #pragma unroll
        for (int o = 16; o; o >>= 1) val += __shfl_down_sync(0xffffffffu, val, o);
        if (lane == 0) redA[r][w] = val;
    }
    __syncthreads();
    float mean[8];
    #pragma unroll
    for (int r = 0; r < 8; r++) {
        float a = ((redA[r][0] + redA[r][1]) + (redA[r][2] + redA[r][3]))
                + ((redA[r][4] + redA[r][5]) + (redA[r][6] + redA[r][7]));
        mean[r] = a * (1.f/256.f);
    }
    float d[8];
    #pragma unroll
    for (int r = 0; r < 8; r++) {
        d[r] = acc[r] - mean[r];
        float val = d[r]*d[r];
        #pragma unroll
        for (int o = 16; o; o >>= 1) val += __shfl_down_sync(0xffffffffu, val, o);
        if (lane == 0) redB[r][w] = val;
    }
    __syncthreads();
    float gv = plg[tid], bv = plb[tid];
    #pragma unroll
    for (int r = 0; r < 8; r++) {
        float a = ((redB[r][0] + redB[r][1]) + (redB[r][2] + redB[r][3]))
                + ((redB[r][4] + redB[r][5]) + (redB[r][6] + redB[r][7]));
        float var = a * (1.f/256.f);
        g_h3[(row0 + r)*256 + tid] = d[r] * rsqrt_acc(var) * gv + bv;
    }
}

// ---------------- interp + LN + fc1 (byte-identical to R13) ----------------
__global__ __launch_bounds__(256) void fc1_kernel(
    const float* __restrict__ ing, const float* __restrict__ inb,
    const float* __restrict__ fc1w, const float* __restrict__ fc1b)
{
    __shared__ float cr[8*256];
    __shared__ float redA[8][8];
    __shared__ float redB[8][8];
    int tid = threadIdx.x;
    int lane = tid & 31, w = tid >> 5;
    int row0 = blockIdx.x * 8;
    float gv = ing[tid], bv = inb[tid];

    float a[8];
    #pragma unroll
    for (int r = 0; r < 8; r++) {
        int row = row0 + r; int b = row / 50, t = row - b*50;
        a[r] = 0.5f * (g_h3[(b*100 + 2*t)*256 + tid] + g_h3[(b*100 + 2*t + 1)*256 + tid]);
    }
    #pragma unroll
    for (int r = 0; r < 8; r++) {
        float val = a[r];
        #pragma unroll
        for (int o = 16; o; o >>= 1) val += __shfl_down_sync(0xffffffffu, val, o);
        if (lane == 0) redA[r][w] = val;
    }
    __syncthreads();
    float mean[8];
    #pragma unroll
    for (int r = 0; r < 8; r++) {
        float s = ((redA[r][0] + redA[r][1]) + (redA[r][2] + redA[r][3]))
                + ((redA[r][4] + redA[r][5]) + (redA[r][6] + redA[r][7]));
        mean[r] = s * (1.f/256.f);
    }
    float d[8];
    #pragma unroll
    for (int r = 0; r < 8; r++) {
        d[r] = a[r] - mean[r];
        float val = d[r]*d[r];
        #pragma unroll
        for (int o = 16; o; o >>= 1) val += __shfl_down_sync(0xffffffffu, val, o);
        if (lane == 0) redB[r][w] = val;
    }
    __syncthreads();
    #pragma unroll
    for (int r = 0; r < 8; r++) {
        float s = ((redB[r][0] + redB[r][1]) + (redB[r][2] + redB[r][3]))
                + ((redB[r][4] + redB[r][5]) + (redB[r][6] + redB[r][7]));
        float var = s * (1.f/256.f);
        cr[r*256 + tid] = d[r] * rsqrt_acc(var) * gv + bv;
    }
    __syncthreads();

    float acc[8];
    #pragma unroll
    for (int r = 0; r < 8; r++) acc[r] = 0.f;
    for (int kc = 0; kc < 16; kc++) {
        float tmp[8];
        int k0 = kc * 16;
        float w0 = fc1w[k0*256 + tid];
        #pragma unroll
        for (int r = 0; r < 8; r++) tmp[r] = cr[r*256 + k0] * w0;
        #pragma unroll
        for (int j = 1; j < 16; j++) {
            float wv = fc1w[(k0+j)*256 + tid];
            #pragma unroll
            for (int r = 0; r < 8; r++) tmp[r] = fmaf(cr[r*256 + k0 + j], wv, tmp[r]);
        }
        #pragma unroll
        for (int r = 0; r < 8; r++) acc[r] += tmp[r];
    }
    float bias = fc1b[tid];
    #pragma unroll
    for (int r = 0; r < 8; r++) g_cur1[(row0 + r)*256 + tid] = acc[r] + bias;
}

// ---------------- scan A-E (byte-identical to R13) ----------------
__global__ __launch_bounds__(256) void scanA_kernel(
    const float* __restrict__ pb1, const float* __restrict__ pt1, float* __restrict__ out)
{
    int b = blockIdx.x, u = threadIdx.x;
    double b1 = (double)fminf(fmaxf(*pb1, 0.f), 1.f), t1 = (double)*pt1;
    double m1 = 0.0;
    const float* curp = &g_cur1[(b*50)*256 + u];
    float* spkp = &out[128 + (b*50)*256 + u];
    for (int t = 0; t < 50; t++) {
        double c = (double)curp[t*256];
        double r1 = (m1 > t1) ? t1 : 0.0;
        m1 = b1*m1 + c - r1;
        spkp[t*256] = (m1 - t1 > 0.0) ? 1.f : 0.f;
    }
}

__global__ __launch_bounds__(256) void scanB_kernel(
    const float* __restrict__ out_spk, const float* __restrict__ fc2w,
    const float* __restrict__ fc2b)
{
    __shared__ float s1s[2][256];
    int tid = threadIdx.x;
    int r0 = blockIdx.x * 2;
    int lr = tid >> 7, j = tid & 127;
    for (int i = tid; i < 512; i += 256)
        s1s[i >> 8][i & 255] = out_spk[128 + (r0 + (i >> 8))*256 + (i & 255)];
    __syncthreads();

    const float* w2col = fc2w + j;
    const float* sp = s1s[lr];
    float acc2 = 0.f;
    #pragma unroll
    for (int kc = 0; kc < 16; kc++) {
        int k0 = kc * 16;
        float tt = sp[k0] * w2col[k0*128];
        #pragma unroll
        for (int jj = 1; jj < 16; jj++)
            tt = fmaf(sp[k0 + jj], w2col[(k0 + jj)*128], tt);
        acc2 += tt;
    }
    g_cur2[(r0 + lr)*128 + j] = acc2 + fc2b[j];
}

__global__ __launch_bounds__(256) void scanC_kernel(
    const float* __restrict__ pb2, const float* __restrict__ pt2)
{
    int idx = blockIdx.x * 256 + threadIdx.x;
    int b = idx >> 7, j = idx & 127;
    double b2 = (double)fminf(fmaxf(*pb2, 0.f), 1.f), t2 = (double)*pt2;
    double m2 = 0.0;
    for (int t = 0; t < 50; t++) {
        double cur2 = (double)g_cur2[(b*50 + t)*128 + j];
        double r2 = (m2 > t2) ? t2 : 0.0;
        m2 = b2*m2 + cur2 - r2;
        g_s2[(b*50 + t)*128 + j] = (m2 - t2 > 0.0) ? 1.f : 0.f;
    }
}

__global__ __launch_bounds__(128) void scanD_kernel(
    const float* __restrict__ fcow, const float* __restrict__ fcob)
{
    __shared__ double red2[4][2];
    int row = blockIdx.x;
    int tid = threadIdx.x, lane = tid & 31, w = tid >> 5;
    float s2 = g_s2[row*128 + tid];
    float fw0 = fcow[tid*2], fw1 = fcow[tid*2 + 1];
    double s2d = (double)s2;
    double v0 = s2d * (double)fw0, v1 = s2d * (double)fw1;
    #pragma unroll
    for (int o = 16; o; o >>= 1) {
        v0 += __shfl_down_sync(0xffffffffu, v0, o);
        v1 += __shfl_down_sync(0xffffffffu, v1, o);
    }
    if (lane == 0) { red2[w][0] = v0; red2[w][1] = v1; }
    __syncthreads();
    if (tid == 0) {
        g_c3[row*2]     = (double)fcob[0] + ((red2[0][0] + red2[1][0]) + (red2[2][0] + red2[3][0]));
        g_c3[row*2 + 1] = (double)fcob[1] + ((red2[0][1] + red2[1][1]) + (red2[2][1] + red2[3][1]));
    }
}

__global__ __launch_bounds__(128) void scanE_kernel(
    const float* __restrict__ pb3, const float* __restrict__ pt3, float* __restrict__ out)
{
    int tid = threadIdx.x;
    int b = tid >> 1, cls = tid & 1;
    double b3 = (double)fminf(fmaxf(*pb3, 0.f), 1.f), t3 = (double)*pt3;
    double mo = 0.0, l = 0.0;
    for (int t = 0; t < 50; t++) {
        double c3 = g_c3[(b*50 + t)*2 + cls];
        double r = (mo > t3) ? t3 : 0.0;
        mo = b3*mo + c3 - r;
        l += mo;
    }
    out[b*2 + cls] = (float)l;
}

// ---------------- launch ----------------
extern "C" void kernel_launch(void* const* d_in, const int* in_sizes, int n_in,
                              void* d_out, int out_size)
{
    const float* x    = (const float*)d_in[0];
    const float* c1w  = (const float*)d_in[1];
    const float* c1b  = (const float*)d_in[2];
    const float* bn1g = (const float*)d_in[3];
    const float* bn1b = (const float*)d_in[4];
    const float* bn1m = (const float*)d_in[5];
    const float* bn1v = (const float*)d_in[6];
    const float* c2w  = (const float*)d_in[7];
    const float* c2b  = (const float*)d_in[8];
    const float* bn2g = (const float*)d_in[9];
    const float* bn2b = (const float*)d_in[10];
    const float* bn2m = (const float*)d_in[11];
    const float* bn2v = (const float*)d_in[12];
    const float* pw   = (const float*)d_in[13];
    const float* pb   = (const float*)d_in[14];
    const float* plg  = (const float*)d_in[15];
    const float* plb  = (const float*)d_in[16];
    const float* ing  = (const float*)d_in[17];
    const float* inb  = (const float*)d_in[18];
    const float* fc1w = (const float*)d_in[19];
    const float* fc1b = (const float*)d_in[20];
    const float* fc2w = (const float*)d_in[21];
    const float* fc2b = (const float*)d_in[22];
    const float* fcow = (const float*)d_in[23];
    const float* fcob = (const float*)d_in[24];
    const float* beta1 = (const float*)d_in[25];
    const float* thr1  = (const float*)d_in[26];
    const float* beta2 = (const float*)d_in[27];
    const float* thr2  = (const float*)d_in[28];
    const float* beta3 = (const float*)d_in[29];
    const float* thr3  = (const float*)d_in[30];
    float* out = (float*)d_out;

    cudaFuncSetAttribute(conv2_kernel, cudaFuncAttributeMaxDynamicSharedMemorySize, CV2_SMEM);

    bsetup_kernel<<<72, 256>>>(c2w, c2b, bn2g, bn2b, bn2m, bn2v);
    conv1_kernel<<<dim3(4, 16, 64), 256>>>(x, c1w, c1b, bn1g, bn1b, bn1m, bn1v);
    conv2_kernel<<<CV2_GRID, 256, CV2_SMEM>>>();
    freqmean_kernel<<<1600, 256>>>();
    proj_kernel<<<800, 256>>>(pw, pb, plg, plb);
    fc1_kernel<<<400, 256>>>(ing, inb, fc1w, fc1b);
    scanA_kernel<<<64, 256>>>(beta1, thr1, out);
    scanB_kernel<<<1600, 256>>>(out, fc2w, fc2b);
    scanC_kernel<<<32, 256>>>(beta2, thr2);
    scanD_kernel<<<3200, 128>>>(fcow, fcob);
    scanE_kernel<<<1, 128>>>(beta3, thr3, out);
}